// round 1
// baseline (speedup 1.0000x reference)
#include <cuda_runtime.h>
#include <cuda_bf16.h>
#include <math.h>

#define U_NODES 200000
#define I_NODES 100000
#define N_NODES 300000
#define E_EDGES 1000000
#define DD 64

// ---------------- scratch (static device globals; no allocation) ----------------
__device__ float g_w[E_EDGES];
__device__ float g_deg[N_NODES];
__device__ float g_dis[N_NODES];
__device__ int   g_cnt[N_NODES];
__device__ int   g_ptr[N_NODES + 1];
__device__ int   g_cur[N_NODES];
__device__ int   g_adj[2 * E_EDGES];
__device__ float g_nrm[2 * E_EDGES];
__device__ __align__(16) float g_xA[(size_t)N_NODES * DD];
__device__ __align__(16) float g_xB[(size_t)N_NODES * DD];
__device__ __align__(16) float g_acc[(size_t)N_NODES * DD];

// ---------------- init: deg = 1 (self loop), cnt = 0 ----------------
__global__ void init_kernel() {
    int i = blockIdx.x * blockDim.x + threadIdx.x;
    if (i < N_NODES) { g_deg[i] = 1.0f; g_cnt[i] = 0; }
}

// ---------------- edge MLP + degree/count accumulation ----------------
__global__ void edge_mlp_kernel(const float* __restrict__ attr,
                                const int* __restrict__ src,
                                const int* __restrict__ dst,
                                const float* __restrict__ W1,
                                const float* __restrict__ b1,
                                const float* __restrict__ W2,
                                const float* __restrict__ b2) {
    __shared__ float sW1[8 * 32];
    __shared__ float sb1[32];
    __shared__ float sW2[32];
    __shared__ float sb2;
    int t = threadIdx.x;
    if (t < 256) sW1[t] = W1[t];
    if (t < 32) { sb1[t] = b1[t]; sW2[t] = W2[t]; }
    if (t == 0) sb2 = b2[0];
    __syncthreads();

    int e = blockIdx.x * blockDim.x + t;
    if (e >= E_EDGES) return;

    const float4* ap = (const float4*)(attr + (size_t)e * 8);
    float4 a0 = ap[0], a1 = ap[1];
    float a[8] = {a0.x, a0.y, a0.z, a0.w, a1.x, a1.y, a1.z, a1.w};

    float z = sb2;
#pragma unroll
    for (int j = 0; j < 32; j++) {
        float h = sb1[j];
#pragma unroll
        for (int k = 0; k < 8; k++) h = fmaf(a[k], sW1[k * 32 + j], h);
        z = fmaf(fmaxf(h, 0.0f), sW2[j], z);
    }
    float w = 1.0f / (1.0f + __expf(-z));
    w = fmaxf(w, 1e-6f);
    g_w[e] = w;

    int s = src[e];
    int d = dst[e] + U_NODES;
    atomicAdd(&g_deg[s], w);
    atomicAdd(&g_deg[d], w);
    atomicAdd(&g_cnt[s], 1);
    atomicAdd(&g_cnt[d], 1);
}

// ---------------- dis = rsqrt(deg) ----------------
__global__ void dis_kernel() {
    int i = blockIdx.x * blockDim.x + threadIdx.x;
    if (i < N_NODES) g_dis[i] = rsqrtf(g_deg[i]);
}

// ---------------- exclusive scan over cnt -> ptr, cursor (single block) ----------------
__global__ void scan_kernel() {
    __shared__ int warp_sums[32];
    __shared__ int s_carry;
    int tid = threadIdx.x;
    if (tid == 0) s_carry = 0;
    __syncthreads();

    for (int base = 0; base < N_NODES; base += 1024) {
        int i = base + tid;
        int v = (i < N_NODES) ? g_cnt[i] : 0;
        // inclusive warp scan
        int x = v;
#pragma unroll
        for (int o = 1; o < 32; o <<= 1) {
            int tmp = __shfl_up_sync(0xffffffffu, x, o);
            if ((tid & 31) >= o) x += tmp;
        }
        if ((tid & 31) == 31) warp_sums[tid >> 5] = x;
        __syncthreads();
        if (tid < 32) {
            int s = warp_sums[tid];
#pragma unroll
            for (int o = 1; o < 32; o <<= 1) {
                int tmp = __shfl_up_sync(0xffffffffu, s, o);
                if (tid >= o) s += tmp;
            }
            warp_sums[tid] = s;
        }
        __syncthreads();
        int wprefix = (tid >= 32) ? warp_sums[(tid >> 5) - 1] : 0;
        int incl = x + wprefix;
        int excl = incl - v;
        int carry = s_carry;
        if (i < N_NODES) {
            g_ptr[i] = carry + excl;
            g_cur[i] = carry + excl;
        }
        __syncthreads();
        if (tid == 1023) s_carry = carry + incl;
        __syncthreads();
    }
    if (tid == 0) g_ptr[N_NODES] = s_carry;
}

// ---------------- scatter edges into CSR ----------------
__global__ void scatter_kernel(const int* __restrict__ src,
                               const int* __restrict__ dst) {
    int e = blockIdx.x * blockDim.x + threadIdx.x;
    if (e >= E_EDGES) return;
    int s = src[e];
    int d = dst[e] + U_NODES;
    float nf = g_dis[s] * g_w[e] * g_dis[d];
    int p1 = atomicAdd(&g_cur[d], 1);
    g_adj[p1] = s;
    g_nrm[p1] = nf;
    int p2 = atomicAdd(&g_cur[s], 1);
    g_adj[p2] = d;
    g_nrm[p2] = nf;
}

// ---------------- user init: l2norm(user_w) -> xA, acc ----------------
__global__ void user_init_kernel(const float* __restrict__ uw) {
    int gw = (blockIdx.x * blockDim.x + threadIdx.x) >> 5;
    int lane = threadIdx.x & 31;
    if (gw >= U_NODES) return;
    float2 v = ((const float2*)uw)[(size_t)gw * 32 + lane];
    float s = v.x * v.x + v.y * v.y;
#pragma unroll
    for (int o = 16; o; o >>= 1) s += __shfl_xor_sync(0xffffffffu, s, o);
    float inv = 1.0f / fmaxf(sqrtf(s), 1e-12f);
    float2 out = make_float2(v.x * inv, v.y * inv);
    ((float2*)g_xA)[(size_t)gw * 32 + lane] = out;
    ((float2*)g_acc)[(size_t)gw * 32 + lane] = out;
}

// ---------------- item init: l2norm([audio, artist+album] @ Wp + bp) ----------------
__global__ void item_init_kernel(const float* __restrict__ audio,
                                 const float* __restrict__ artw,
                                 const float* __restrict__ albw,
                                 const int* __restrict__ aid,
                                 const int* __restrict__ alid,
                                 const float* __restrict__ Wp,
                                 const float* __restrict__ bp) {
    __shared__ float sWp[128 * 64];
    int t = threadIdx.x;
    for (int i = t; i < 128 * 64; i += blockDim.x) sWp[i] = Wp[i];
    __syncthreads();

    int lane = t & 31;
    int warp = t >> 5;
    int nwarp = (gridDim.x * blockDim.x) >> 5;
    const float2* Wp2 = (const float2*)sWp;
    float bp0 = bp[2 * lane];
    float bp1 = bp[2 * lane + 1];

    for (int item = blockIdx.x * (blockDim.x >> 5) + warp; item < I_NODES; item += nwarp) {
        float4 r;
        if (lane < 16) {
            r = ((const float4*)(audio + (size_t)item * 64))[lane];
        } else {
            int a = aid[item], al = alid[item];
            float4 x1 = ((const float4*)(artw + (size_t)a * 64))[lane - 16];
            float4 x2 = ((const float4*)(albw + (size_t)al * 64))[lane - 16];
            r = make_float4(x1.x + x2.x, x1.y + x2.y, x1.z + x2.z, x1.w + x2.w);
        }
        float acc0 = bp0, acc1 = bp1;
#pragma unroll
        for (int sl = 0; sl < 32; sl++) {
            float v0 = __shfl_sync(0xffffffffu, r.x, sl);
            float v1 = __shfl_sync(0xffffffffu, r.y, sl);
            float v2 = __shfl_sync(0xffffffffu, r.z, sl);
            float v3 = __shfl_sync(0xffffffffu, r.w, sl);
            int k = sl * 4;
            float2 w0 = Wp2[(k + 0) * 32 + lane];
            float2 w1 = Wp2[(k + 1) * 32 + lane];
            float2 w2 = Wp2[(k + 2) * 32 + lane];
            float2 w3 = Wp2[(k + 3) * 32 + lane];
            acc0 = fmaf(v0, w0.x, acc0); acc1 = fmaf(v0, w0.y, acc1);
            acc0 = fmaf(v1, w1.x, acc0); acc1 = fmaf(v1, w1.y, acc1);
            acc0 = fmaf(v2, w2.x, acc0); acc1 = fmaf(v2, w2.y, acc1);
            acc0 = fmaf(v3, w3.x, acc0); acc1 = fmaf(v3, w3.y, acc1);
        }
        float s = acc0 * acc0 + acc1 * acc1;
#pragma unroll
        for (int o = 16; o; o >>= 1) s += __shfl_xor_sync(0xffffffffu, s, o);
        float inv = 1.0f / fmaxf(sqrtf(s), 1e-12f);
        float2 out = make_float2(acc0 * inv, acc1 * inv);
        size_t n = (size_t)(U_NODES + item);
        ((float2*)g_xA)[n * 32 + lane] = out;
        ((float2*)g_acc)[n * 32 + lane] = out;
    }
}

// ---------------- one LGConv layer: y = A_norm @ x ; acc += y ----------------
__global__ void gather_kernel(int aToB) {
    int n = (blockIdx.x * blockDim.x + threadIdx.x) >> 5;
    if (n >= N_NODES) return;
    int lane = threadIdx.x & 31;

    const float* xin = aToB ? g_xA : g_xB;
    float* xout = aToB ? g_xB : g_xA;

    const float2* xr = (const float2*)xin;
    float selfv = g_dis[n];
    selfv *= selfv;

    float2 a = xr[(size_t)n * 32 + lane];
    a.x *= selfv;
    a.y *= selfv;

    int e = g_ptr[n];
    int end = g_ptr[n + 1];
    for (; e + 1 < end; e += 2) {
        int j0 = __ldg(&g_adj[e]);
        int j1 = __ldg(&g_adj[e + 1]);
        float v0 = __ldg(&g_nrm[e]);
        float v1 = __ldg(&g_nrm[e + 1]);
        float2 x0 = xr[(size_t)j0 * 32 + lane];
        float2 x1 = xr[(size_t)j1 * 32 + lane];
        a.x = fmaf(v0, x0.x, a.x); a.y = fmaf(v0, x0.y, a.y);
        a.x = fmaf(v1, x1.x, a.x); a.y = fmaf(v1, x1.y, a.y);
    }
    if (e < end) {
        int j0 = __ldg(&g_adj[e]);
        float v0 = __ldg(&g_nrm[e]);
        float2 x0 = xr[(size_t)j0 * 32 + lane];
        a.x = fmaf(v0, x0.x, a.x); a.y = fmaf(v0, x0.y, a.y);
    }

    ((float2*)xout)[(size_t)n * 32 + lane] = a;
    float2* ac = (float2*)g_acc;
    float2 c = ac[(size_t)n * 32 + lane];
    c.x += a.x;
    c.y += a.y;
    ac[(size_t)n * 32 + lane] = c;
}

// ---------------- final: out = l2norm(acc / 4) ----------------
__global__ void final_kernel(float* __restrict__ out) {
    int n = (blockIdx.x * blockDim.x + threadIdx.x) >> 5;
    if (n >= N_NODES) return;
    int lane = threadIdx.x & 31;
    float2 c = ((const float2*)g_acc)[(size_t)n * 32 + lane];
    c.x *= 0.25f;
    c.y *= 0.25f;
    float s = c.x * c.x + c.y * c.y;
#pragma unroll
    for (int o = 16; o; o >>= 1) s += __shfl_xor_sync(0xffffffffu, s, o);
    float inv = 1.0f / fmaxf(sqrtf(s), 1e-12f);
    ((float2*)out)[(size_t)n * 32 + lane] = make_float2(c.x * inv, c.y * inv);
}

extern "C" void kernel_launch(void* const* d_in, const int* in_sizes, int n_in,
                              void* d_out, int out_size) {
    const int*   edge_src   = (const int*)d_in[0];
    const int*   edge_dst   = (const int*)d_in[1];
    const float* edge_attr  = (const float*)d_in[2];
    const float* user_w     = (const float*)d_in[3];
    const float* artist_w   = (const float*)d_in[4];
    const float* album_w    = (const float*)d_in[5];
    const float* item_audio = (const float*)d_in[6];
    const int*   artist_ids = (const int*)d_in[7];
    const int*   album_ids  = (const int*)d_in[8];
    const float* Wp         = (const float*)d_in[9];
    const float* bp         = (const float*)d_in[10];
    const float* W1         = (const float*)d_in[11];
    const float* b1         = (const float*)d_in[12];
    const float* W2         = (const float*)d_in[13];
    const float* b2         = (const float*)d_in[14];
    float* out = (float*)d_out;

    const int TPB = 256;

    // graph weight + structure build
    init_kernel<<<(N_NODES + TPB - 1) / TPB, TPB>>>();
    edge_mlp_kernel<<<(E_EDGES + TPB - 1) / TPB, TPB>>>(edge_attr, edge_src, edge_dst,
                                                        W1, b1, W2, b2);
    // node feature init (independent of graph build; same stream serializes)
    user_init_kernel<<<(U_NODES * 32 + TPB - 1) / TPB, TPB>>>(user_w);
    item_init_kernel<<<1184, TPB>>>(item_audio, artist_w, album_w,
                                    artist_ids, album_ids, Wp, bp);

    dis_kernel<<<(N_NODES + TPB - 1) / TPB, TPB>>>();
    scan_kernel<<<1, 1024>>>();
    scatter_kernel<<<(E_EDGES + TPB - 1) / TPB, TPB>>>(edge_src, edge_dst);

    // 3 propagation layers (ping-pong xA <-> xB), acc += y each layer
    int nblocks = (N_NODES * 32 + TPB - 1) / TPB;
    gather_kernel<<<nblocks, TPB>>>(1); // xA -> xB
    gather_kernel<<<nblocks, TPB>>>(0); // xB -> xA
    gather_kernel<<<nblocks, TPB>>>(1); // xA -> xB

    final_kernel<<<nblocks, TPB>>>(out);
}

// round 3
// speedup vs baseline: 1.9768x; 1.9768x over previous
#include <cuda_runtime.h>
#include <cuda_bf16.h>
#include <math.h>

#define U_NODES 200000
#define I_NODES 100000
#define N_NODES 300000
#define E_EDGES 1000000
#define DD 64
#define NB_SCAN 293   // ceil(300000/1024)

// ---------------- scratch (static device globals; no allocation) ----------------
__device__ float g_w[E_EDGES];
__device__ float g_deg[N_NODES];
__device__ float g_dis[N_NODES];
__device__ int   g_cnt[N_NODES];
__device__ int   g_ptr[N_NODES + 1];
__device__ int   g_cur[N_NODES];
__device__ int   g_bsum[NB_SCAN];
__device__ int   g_boff[NB_SCAN];
__device__ int   g_adj[2 * E_EDGES];
__device__ float g_nrm[2 * E_EDGES];
__device__ __align__(16) float g_xA[(size_t)N_NODES * DD];
__device__ __align__(16) float g_xB[(size_t)N_NODES * DD];
__device__ __align__(16) float g_acc[(size_t)N_NODES * DD];

// ---------------- init: deg = 1 (self loop), cnt = 0 ----------------
__global__ void init_kernel() {
    int i = blockIdx.x * blockDim.x + threadIdx.x;
    if (i < N_NODES) { g_deg[i] = 1.0f; g_cnt[i] = 0; }
}

// ---------------- edge MLP + degree/count accumulation ----------------
__global__ void edge_mlp_kernel(const float* __restrict__ attr,
                                const int* __restrict__ src,
                                const int* __restrict__ dst,
                                const float* __restrict__ W1,
                                const float* __restrict__ b1,
                                const float* __restrict__ W2,
                                const float* __restrict__ b2) {
    __shared__ float sW1[8 * 32];
    __shared__ float sb1[32];
    __shared__ float sW2[32];
    __shared__ float sb2;
    int t = threadIdx.x;
    if (t < 256) sW1[t] = W1[t];
    if (t < 32) { sb1[t] = b1[t]; sW2[t] = W2[t]; }
    if (t == 0) sb2 = b2[0];
    __syncthreads();

    int e = blockIdx.x * blockDim.x + t;
    if (e >= E_EDGES) return;

    const float4* ap = (const float4*)(attr + (size_t)e * 8);
    float4 a0 = ap[0], a1 = ap[1];
    float a[8] = {a0.x, a0.y, a0.z, a0.w, a1.x, a1.y, a1.z, a1.w};

    float z = sb2;
#pragma unroll
    for (int j = 0; j < 32; j++) {
        float h = sb1[j];
#pragma unroll
        for (int k = 0; k < 8; k++) h = fmaf(a[k], sW1[k * 32 + j], h);
        z = fmaf(fmaxf(h, 0.0f), sW2[j], z);
    }
    float w = 1.0f / (1.0f + __expf(-z));
    w = fmaxf(w, 1e-6f);
    g_w[e] = w;

    int s = src[e];
    int d = dst[e] + U_NODES;
    atomicAdd(&g_deg[s], w);
    atomicAdd(&g_deg[d], w);
    atomicAdd(&g_cnt[s], 1);
    atomicAdd(&g_cnt[d], 1);
}

// ---------------- dis = rsqrt(deg) ----------------
__global__ void dis_kernel() {
    int i = blockIdx.x * blockDim.x + threadIdx.x;
    if (i < N_NODES) g_dis[i] = rsqrtf(g_deg[i]);
}

// ---------------- multi-block scan: phase 1, per-block sums ----------------
__global__ void blocksum_kernel() {
    __shared__ int ws[32];
    int t = threadIdx.x;
    int i = blockIdx.x * 1024 + t;
    int v = (i < N_NODES) ? g_cnt[i] : 0;
#pragma unroll
    for (int o = 16; o; o >>= 1) v += __shfl_xor_sync(0xffffffffu, v, o);
    if ((t & 31) == 0) ws[t >> 5] = v;
    __syncthreads();
    if (t < 32) {
        int s = ws[t];
#pragma unroll
        for (int o = 16; o; o >>= 1) s += __shfl_xor_sync(0xffffffffu, s, o);
        if (t == 0) g_bsum[blockIdx.x] = s;
    }
}

// ---------------- phase 2: exclusive scan of 293 block sums (1 block) ----------------
__global__ void bscan_kernel() {
    __shared__ int ws[16];
    int t = threadIdx.x; // 512 threads
    int v = (t < NB_SCAN) ? g_bsum[t] : 0;
    int x = v;
#pragma unroll
    for (int o = 1; o < 32; o <<= 1) {
        int tmp = __shfl_up_sync(0xffffffffu, x, o);
        if ((t & 31) >= o) x += tmp;
    }
    if ((t & 31) == 31) ws[t >> 5] = x;
    __syncthreads();
    if (t < 16) {
        int s = ws[t];
#pragma unroll
        for (int o = 1; o < 16; o <<= 1) {
            int tmp = __shfl_up_sync(0x0000ffffu, s, o);
            if (t >= o) s += tmp;
        }
        ws[t] = s;
    }
    __syncthreads();
    int wp = (t >= 32) ? ws[(t >> 5) - 1] : 0;
    int incl = x + wp;
    if (t < NB_SCAN) g_boff[t] = incl - v;
    if (t == NB_SCAN - 1) g_ptr[N_NODES] = incl;
}

// ---------------- phase 3: per-block local scan + offset -> ptr, cur ----------------
__global__ void ptr_kernel() {
    __shared__ int ws[32];
    int t = threadIdx.x;
    int i = blockIdx.x * 1024 + t;
    int v = (i < N_NODES) ? g_cnt[i] : 0;
    int x = v;
#pragma unroll
    for (int o = 1; o < 32; o <<= 1) {
        int tmp = __shfl_up_sync(0xffffffffu, x, o);
        if ((t & 31) >= o) x += tmp;
    }
    if ((t & 31) == 31) ws[t >> 5] = x;
    __syncthreads();
    if (t < 32) {
        int s = ws[t];
#pragma unroll
        for (int o = 1; o < 32; o <<= 1) {
            int tmp = __shfl_up_sync(0xffffffffu, s, o);
            if (t >= o) s += tmp;
        }
        ws[t] = s;
    }
    __syncthreads();
    int wp = (t >= 32) ? ws[(t >> 5) - 1] : 0;
    int excl = (x - v) + wp + g_boff[blockIdx.x];
    if (i < N_NODES) { g_ptr[i] = excl; g_cur[i] = excl; }
}

// ---------------- scatter edges into CSR ----------------
__global__ void scatter_kernel(const int* __restrict__ src,
                               const int* __restrict__ dst) {
    int e = blockIdx.x * blockDim.x + threadIdx.x;
    if (e >= E_EDGES) return;
    int s = src[e];
    int d = dst[e] + U_NODES;
    float nf = g_dis[s] * g_w[e] * g_dis[d];
    int p1 = atomicAdd(&g_cur[d], 1);
    g_adj[p1] = s;
    g_nrm[p1] = nf;
    int p2 = atomicAdd(&g_cur[s], 1);
    g_adj[p2] = d;
    g_nrm[p2] = nf;
}

// ---------------- user init: l2norm(user_w) -> xA  (16 lanes/node, float4) ----------------
__global__ void user_init_kernel(const float* __restrict__ uw) {
    int gid = blockIdx.x * blockDim.x + threadIdx.x;
    int n = gid >> 4;
    if (n >= U_NODES) return;
    int lane = threadIdx.x & 15;
    float4 v = ((const float4*)uw)[(size_t)n * 16 + lane];
    float s = v.x * v.x + v.y * v.y + v.z * v.z + v.w * v.w;
#pragma unroll
    for (int o = 8; o; o >>= 1) s += __shfl_xor_sync(0xffffffffu, s, o);
    float inv = 1.0f / fmaxf(sqrtf(s), 1e-12f);
    float4 out = make_float4(v.x * inv, v.y * inv, v.z * inv, v.w * inv);
    ((float4*)g_xA)[(size_t)n * 16 + lane] = out;
}

// ---------------- item init: register-tiled GEMM (64 items/block, 4x4 tile) ----------------
__global__ void item_init_kernel(const float* __restrict__ audio,
                                 const float* __restrict__ artw,
                                 const float* __restrict__ albw,
                                 const int* __restrict__ aid,
                                 const int* __restrict__ alid,
                                 const float* __restrict__ Wp,
                                 const float* __restrict__ bp) {
    __shared__ __align__(16) float sIn[128 * 64];   // [k][item]  32 KB
    __shared__ float sRed[64 * 17];                 // per-item partial sums (padded)
    __shared__ float sInv[64];
    int t = threadIdx.x;
    int item0 = blockIdx.x * 64;
    int w = t >> 5, l = t & 31;
    int item_local = ((w & 1) << 5) + l;     // 0..63, lanes span items
    int item = item0 + item_local;
    bool valid = item < I_NODES;
    int cbase = w >> 1;                      // 0..3

    int a_id = valid ? aid[item] : 0;
    int al_id = valid ? alid[item] : 0;

#pragma unroll
    for (int j = 0; j < 8; j++) {
        int c = cbase + 4 * j;               // float4 chunk 0..31
        float4 v;
        if (!valid) v = make_float4(0.f, 0.f, 0.f, 0.f);
        else if (c < 16) v = ((const float4*)(audio + (size_t)item * 64))[c];
        else {
            float4 x1 = ((const float4*)(artw + (size_t)a_id * 64))[c - 16];
            float4 x2 = ((const float4*)(albw + (size_t)al_id * 64))[c - 16];
            v = make_float4(x1.x + x2.x, x1.y + x2.y, x1.z + x2.z, x1.w + x2.w);
        }
        int k = c * 4;
        sIn[(k + 0) * 64 + item_local] = v.x;
        sIn[(k + 1) * 64 + item_local] = v.y;
        sIn[(k + 2) * 64 + item_local] = v.z;
        sIn[(k + 3) * 64 + item_local] = v.w;
    }
    __syncthreads();

    int tx = t & 15;   // column group (cols tx*4..+3)
    int ty = t >> 4;   // item group   (items ty*4..+3)
    float4 bp4 = ((const float4*)bp)[tx];
    float acc[4][4];
#pragma unroll
    for (int i = 0; i < 4; i++) {
        acc[i][0] = bp4.x; acc[i][1] = bp4.y; acc[i][2] = bp4.z; acc[i][3] = bp4.w;
    }
    const float4* Wp4 = (const float4*)Wp;
#pragma unroll 4
    for (int k = 0; k < 128; k++) {
        float4 in4 = *(const float4*)(sIn + k * 64 + ty * 4);
        float4 w4 = __ldg(Wp4 + k * 16 + tx);   // L1-resident (32 KB)
        float vi[4] = {in4.x, in4.y, in4.z, in4.w};
#pragma unroll
        for (int i = 0; i < 4; i++) {
            acc[i][0] = fmaf(vi[i], w4.x, acc[i][0]);
            acc[i][1] = fmaf(vi[i], w4.y, acc[i][1]);
            acc[i][2] = fmaf(vi[i], w4.z, acc[i][2]);
            acc[i][3] = fmaf(vi[i], w4.w, acc[i][3]);
        }
    }
#pragma unroll
    for (int i = 0; i < 4; i++) {
        float p = acc[i][0] * acc[i][0] + acc[i][1] * acc[i][1]
                + acc[i][2] * acc[i][2] + acc[i][3] * acc[i][3];
        sRed[(ty * 4 + i) * 17 + tx] = p;
    }
    __syncthreads();
    if (t < 64) {
        float s = 0.f;
#pragma unroll
        for (int q = 0; q < 16; q++) s += sRed[t * 17 + q];
        sInv[t] = 1.0f / fmaxf(sqrtf(s), 1e-12f);
    }
    __syncthreads();
#pragma unroll
    for (int i = 0; i < 4; i++) {
        int il = ty * 4 + i;
        int it = item0 + il;
        if (it < I_NODES) {
            float inv = sInv[il];
            float4 o = make_float4(acc[i][0] * inv, acc[i][1] * inv,
                                   acc[i][2] * inv, acc[i][3] * inv);
            ((float4*)g_xA)[(size_t)(U_NODES + it) * 16 + tx] = o;
        }
    }
}

// ---------------- one LGConv layer (16 lanes/node, float4, unroll 4) ----------------
// MODE 0: layer1  xA->xB — write xout, write acc = self_raw + a (no acc read)
// MODE 1: layer2  xB->xA — write xout, acc += a
// MODE 2: layer3  xA->out — fused final: out = l2norm((acc + a)/4), no xout write
// Buffers are selected INSIDE device code (device symbols are not valid host ptrs).
template<int MODE>
__global__ void gather_kernel(float* __restrict__ outp) {
    const float4* xin = (MODE == 1) ? (const float4*)g_xB : (const float4*)g_xA;
    float4* xout = (MODE == 0) ? (float4*)g_xB : (float4*)g_xA;

    int gid = blockIdx.x * blockDim.x + threadIdx.x;
    int n = gid >> 4;
    if (n >= N_NODES) return;
    int lane = threadIdx.x & 15;

    float4 self = xin[(size_t)n * 16 + lane];
    float dv = g_dis[n];
    float sw = dv * dv;
    float4 a = make_float4(self.x * sw, self.y * sw, self.z * sw, self.w * sw);
    float4 a2 = make_float4(0.f, 0.f, 0.f, 0.f);

    int e = g_ptr[n];
    int end = g_ptr[n + 1];
    for (; e + 4 <= end; e += 4) {
        int j0 = __ldg(g_adj + e + 0);
        int j1 = __ldg(g_adj + e + 1);
        int j2 = __ldg(g_adj + e + 2);
        int j3 = __ldg(g_adj + e + 3);
        float v0 = __ldg(g_nrm + e + 0);
        float v1 = __ldg(g_nrm + e + 1);
        float v2 = __ldg(g_nrm + e + 2);
        float v3 = __ldg(g_nrm + e + 3);
        float4 x0 = xin[(size_t)j0 * 16 + lane];
        float4 x1 = xin[(size_t)j1 * 16 + lane];
        float4 x2 = xin[(size_t)j2 * 16 + lane];
        float4 x3 = xin[(size_t)j3 * 16 + lane];
        a.x  = fmaf(v0, x0.x, a.x);  a.y  = fmaf(v0, x0.y, a.y);
        a.z  = fmaf(v0, x0.z, a.z);  a.w  = fmaf(v0, x0.w, a.w);
        a.x  = fmaf(v1, x1.x, a.x);  a.y  = fmaf(v1, x1.y, a.y);
        a.z  = fmaf(v1, x1.z, a.z);  a.w  = fmaf(v1, x1.w, a.w);
        a2.x = fmaf(v2, x2.x, a2.x); a2.y = fmaf(v2, x2.y, a2.y);
        a2.z = fmaf(v2, x2.z, a2.z); a2.w = fmaf(v2, x2.w, a2.w);
        a2.x = fmaf(v3, x3.x, a2.x); a2.y = fmaf(v3, x3.y, a2.y);
        a2.z = fmaf(v3, x3.z, a2.z); a2.w = fmaf(v3, x3.w, a2.w);
    }
    for (; e < end; e++) {
        int j0 = __ldg(g_adj + e);
        float v0 = __ldg(g_nrm + e);
        float4 x0 = xin[(size_t)j0 * 16 + lane];
        a.x = fmaf(v0, x0.x, a.x); a.y = fmaf(v0, x0.y, a.y);
        a.z = fmaf(v0, x0.z, a.z); a.w = fmaf(v0, x0.w, a.w);
    }
    a.x += a2.x; a.y += a2.y; a.z += a2.z; a.w += a2.w;

    if (MODE == 0) {
        xout[(size_t)n * 16 + lane] = a;
        float4 c = make_float4(self.x + a.x, self.y + a.y, self.z + a.z, self.w + a.w);
        ((float4*)g_acc)[(size_t)n * 16 + lane] = c;
    } else if (MODE == 1) {
        xout[(size_t)n * 16 + lane] = a;
        float4 c = ((const float4*)g_acc)[(size_t)n * 16 + lane];
        c.x += a.x; c.y += a.y; c.z += a.z; c.w += a.w;
        ((float4*)g_acc)[(size_t)n * 16 + lane] = c;
    } else {
        float4 c = ((const float4*)g_acc)[(size_t)n * 16 + lane];
        c.x = (c.x + a.x) * 0.25f;
        c.y = (c.y + a.y) * 0.25f;
        c.z = (c.z + a.z) * 0.25f;
        c.w = (c.w + a.w) * 0.25f;
        float s = c.x * c.x + c.y * c.y + c.z * c.z + c.w * c.w;
#pragma unroll
        for (int o = 8; o; o >>= 1) s += __shfl_xor_sync(0xffffffffu, s, o);
        float inv = 1.0f / fmaxf(sqrtf(s), 1e-12f);
        ((float4*)outp)[(size_t)n * 16 + lane] =
            make_float4(c.x * inv, c.y * inv, c.z * inv, c.w * inv);
    }
}

extern "C" void kernel_launch(void* const* d_in, const int* in_sizes, int n_in,
                              void* d_out, int out_size) {
    const int*   edge_src   = (const int*)d_in[0];
    const int*   edge_dst   = (const int*)d_in[1];
    const float* edge_attr  = (const float*)d_in[2];
    const float* user_w     = (const float*)d_in[3];
    const float* artist_w   = (const float*)d_in[4];
    const float* album_w    = (const float*)d_in[5];
    const float* item_audio = (const float*)d_in[6];
    const int*   artist_ids = (const int*)d_in[7];
    const int*   album_ids  = (const int*)d_in[8];
    const float* Wp         = (const float*)d_in[9];
    const float* bp         = (const float*)d_in[10];
    const float* W1         = (const float*)d_in[11];
    const float* b1         = (const float*)d_in[12];
    const float* W2         = (const float*)d_in[13];
    const float* b2         = (const float*)d_in[14];
    float* out = (float*)d_out;

    const int TPB = 256;

    init_kernel<<<(N_NODES + TPB - 1) / TPB, TPB>>>();
    edge_mlp_kernel<<<(E_EDGES + TPB - 1) / TPB, TPB>>>(edge_attr, edge_src, edge_dst,
                                                        W1, b1, W2, b2);
    user_init_kernel<<<(U_NODES * 16 + TPB - 1) / TPB, TPB>>>(user_w);
    item_init_kernel<<<(I_NODES + 63) / 64, TPB>>>(item_audio, artist_w, album_w,
                                                   artist_ids, album_ids, Wp, bp);

    dis_kernel<<<(N_NODES + TPB - 1) / TPB, TPB>>>();
    blocksum_kernel<<<NB_SCAN, 1024>>>();
    bscan_kernel<<<1, 512>>>();
    ptr_kernel<<<NB_SCAN, 1024>>>();
    scatter_kernel<<<(E_EDGES + TPB - 1) / TPB, TPB>>>(edge_src, edge_dst);

    int nblocks = (N_NODES * 16 + TPB - 1) / TPB;
    gather_kernel<0><<<nblocks, TPB>>>(nullptr);
    gather_kernel<1><<<nblocks, TPB>>>(nullptr);
    gather_kernel<2><<<nblocks, TPB>>>(out);
}